// round 11
// baseline (speedup 1.0000x reference)
#include <cuda_runtime.h>

#define BS 4
#define SEQ 2048
#define HID 1024
#define HEADS 16
#define DH 64
#define RANK 16
#define M_TOT (BS*SEQ)
#define LOG2E 1.4426950408889634f

// Scratch (allocation-free rule: __device__ globals)
__device__ float g_T[3 * M_TOT * RANK];                       // 1.5 MB
__device__ float g_qkv[3LL * BS * HEADS * SEQ * DH];          // 96 MB: [p][b][h][s][d]

__device__ __forceinline__ float f2tf(float x) {
    unsigned u;
    asm("cvt.rna.tf32.f32 %0, %1;" : "=r"(u) : "f"(x));
    return __uint_as_float(u);
}
__device__ __forceinline__ unsigned fbits(float x) { return __float_as_uint(x); }

__device__ __forceinline__ void mma8(float* c, const unsigned* a, unsigned b0, unsigned b1) {
    asm volatile(
        "mma.sync.aligned.m16n8k8.row.col.f32.tf32.tf32.f32 "
        "{%0,%1,%2,%3},{%4,%5,%6,%7},{%8,%9},{%0,%1,%2,%3};"
        : "+f"(c[0]), "+f"(c[1]), "+f"(c[2]), "+f"(c[3])
        : "r"(a[0]), "r"(a[1]), "r"(a[2]), "r"(a[3]), "r"(b0), "r"(b1));
}

// ---------------- K1: T[p][m][r] = (1/RANK) * sum_k x[m][k] * A_p[r][k] ----------------
__global__ __launch_bounds__(256) void lora_t_kernel(
    const float* __restrict__ x,
    const float* __restrict__ Aq, const float* __restrict__ Ak, const float* __restrict__ Av)
{
    int p = blockIdx.y;
    const float* A = (p == 0) ? Aq : ((p == 1) ? Ak : Av);
    int w = threadIdx.x >> 5, lane = threadIdx.x & 31;
    int m = blockIdx.x * 8 + w;
    const float* xr = x + (size_t)m * HID;
    float xv[32];
#pragma unroll
    for (int i = 0; i < 32; i++) xv[i] = xr[lane + 32 * i];
#pragma unroll 1
    for (int r = 0; r < RANK; r++) {
        const float* Ar = A + r * HID;
        float acc = 0.f;
#pragma unroll
        for (int i = 0; i < 32; i++) acc += xv[i] * Ar[lane + 32 * i];
#pragma unroll
        for (int off = 16; off; off >>= 1) acc += __shfl_xor_sync(0xffffffffu, acc, off);
        if (lane == 0) g_T[((size_t)p * M_TOT + m) * RANK + r] = acc * (1.0f / RANK);
    }
}

// ---------------- K2: QKV projection GEMM (tf32 mma), bias + LoRA fused --------------
// out[p][b][h][s][d] = x @ W_p^T + bias_p + T_p @ BL_p^T
__global__ __launch_bounds__(256) void proj_kernel(
    const float* __restrict__ x,
    const float* __restrict__ Wq, const float* __restrict__ bq, const float* __restrict__ BLq,
    const float* __restrict__ Wk, const float* __restrict__ bk, const float* __restrict__ BLk,
    const float* __restrict__ Wv, const float* __restrict__ bv, const float* __restrict__ BLv)
{
    __shared__ float As[128 * 36];  // x tile   [m][k], stride 36 -> conflict-free frags
    __shared__ float Bs[128 * 36];  // W tile   [n][k]
    int p = blockIdx.z;
    const float* W    = (p == 0) ? Wq  : ((p == 1) ? Wk  : Wv);
    const float* bias = (p == 0) ? bq  : ((p == 1) ? bk  : bv);
    const float* BL   = (p == 0) ? BLq : ((p == 1) ? BLk : BLv);

    int tid = threadIdx.x, lane = tid & 31, warp = tid >> 5;
    int wm = warp & 3, wn = warp >> 2;               // 4x2 warp grid -> warp tile 32x64
    int mbase = blockIdx.x * 128, nbase = blockIdx.y * 128;

    float acc[2][8][4];
#pragma unroll
    for (int mt = 0; mt < 2; mt++)
#pragma unroll
        for (int nt = 0; nt < 8; nt++)
#pragma unroll
            for (int i = 0; i < 4; i++) acc[mt][nt][i] = 0.f;

    for (int kt = 0; kt < HID / 32; kt++) {
        int kb = kt * 32;
#pragma unroll
        for (int i = 0; i < 4; i++) {
            int u = tid + i * 256;
            int row = u >> 3, c4 = (u & 7) * 4;
            float4 va = *reinterpret_cast<const float4*>(x + (size_t)(mbase + row) * HID + kb + c4);
            float* da = &As[row * 36 + c4];
            da[0] = f2tf(va.x); da[1] = f2tf(va.y); da[2] = f2tf(va.z); da[3] = f2tf(va.w);
            float4 vb = *reinterpret_cast<const float4*>(W + (size_t)(nbase + row) * HID + kb + c4);
            float* db = &Bs[row * 36 + c4];
            db[0] = f2tf(vb.x); db[1] = f2tf(vb.y); db[2] = f2tf(vb.z); db[3] = f2tf(vb.w);
        }
        __syncthreads();
#pragma unroll
        for (int ks = 0; ks < 4; ks++) {
            unsigned a[2][4];
#pragma unroll
            for (int mt = 0; mt < 2; mt++) {
                int r = wm * 32 + mt * 16 + (lane >> 2);
                int c = ks * 8 + (lane & 3);
                a[mt][0] = fbits(As[r * 36 + c]);
                a[mt][1] = fbits(As[(r + 8) * 36 + c]);
                a[mt][2] = fbits(As[r * 36 + c + 4]);
                a[mt][3] = fbits(As[(r + 8) * 36 + c + 4]);
            }
#pragma unroll
            for (int nt = 0; nt < 8; nt++) {
                int col = wn * 64 + nt * 8 + (lane >> 2);
                unsigned b0 = fbits(Bs[col * 36 + ks * 8 + (lane & 3)]);
                unsigned b1 = fbits(Bs[col * 36 + ks * 8 + 4 + (lane & 3)]);
                mma8(acc[0][nt], a[0], b0, b1);
                mma8(acc[1][nt], a[1], b0, b1);
            }
        }
        __syncthreads();
    }

    // LoRA correction: 16 extra K-columns (T already scaled by 1/RANK)
#pragma unroll
    for (int i = 0; i < 8; i++) {
        int u = tid + i * 256;
        int row = u >> 4, c = u & 15;
        As[row * 36 + c] = f2tf(g_T[((size_t)p * M_TOT + mbase + row) * RANK + c]);
        Bs[row * 36 + c] = f2tf(BL[(size_t)(nbase + row) * RANK + c]);
    }
    __syncthreads();
#pragma unroll
    for (int ks = 0; ks < 2; ks++) {
        unsigned a[2][4];
#pragma unroll
        for (int mt = 0; mt < 2; mt++) {
            int r = wm * 32 + mt * 16 + (lane >> 2);
            int c = ks * 8 + (lane & 3);
            a[mt][0] = fbits(As[r * 36 + c]);
            a[mt][1] = fbits(As[(r + 8) * 36 + c]);
            a[mt][2] = fbits(As[r * 36 + c + 4]);
            a[mt][3] = fbits(As[(r + 8) * 36 + c + 4]);
        }
#pragma unroll
        for (int nt = 0; nt < 8; nt++) {
            int col = wn * 64 + nt * 8 + (lane >> 2);
            unsigned b0 = fbits(Bs[col * 36 + ks * 8 + (lane & 3)]);
            unsigned b1 = fbits(Bs[col * 36 + ks * 8 + 4 + (lane & 3)]);
            mma8(acc[0][nt], a[0], b0, b1);
            mma8(acc[1][nt], a[1], b0, b1);
        }
    }

    // Epilogue: bias, permute to [p][b][h][s][d]
#pragma unroll
    for (int mt = 0; mt < 2; mt++) {
#pragma unroll
        for (int half = 0; half < 2; half++) {
            int m = mbase + wm * 32 + mt * 16 + (lane >> 2) + half * 8;
            int bb = m >> 11, s = m & (SEQ - 1);
#pragma unroll
            for (int nt = 0; nt < 8; nt++) {
                int n = nbase + wn * 64 + nt * 8 + 2 * (lane & 3);
                float2 v;
                v.x = acc[mt][nt][half * 2 + 0] + bias[n];
                v.y = acc[mt][nt][half * 2 + 1] + bias[n + 1];
                int hh = n >> 6, d = n & 63;
                *reinterpret_cast<float2*>(
                    &g_qkv[((((size_t)p * BS + bb) * HEADS + hh) * SEQ + s) * DH + d]) = v;
            }
        }
    }
}

// ---------------- K3: flash attention (tf32 mma, fp32 online softmax) ----------------
// grid (SEQ/128, BS*HEADS), 256 threads, 8 warps x 16 q-rows
__global__ __launch_bounds__(256) void flash_kernel(const float* __restrict__ mask,
                                                    float* __restrict__ out)
{
    extern __shared__ float sm[];
    float* Ps = sm;                  // 128*132 (also Q staging)
    float* Ks = sm + 128 * 132;      // 128*68
    float* Vs = Ks + 128 * 68;       // 128*68
    float* Ms = Vs + 128 * 68;       // 128

    int tid = threadIdx.x, lane = tid & 31, w = tid >> 5;
    int qt = blockIdx.x, bh = blockIdx.y;
    int b = bh >> 4, h = bh & 15;
    const float* Qg = g_qkv + ((size_t)(b * HEADS + h)) * SEQ * DH;
    const float* Kg = g_qkv + ((size_t)((BS + b) * HEADS + h)) * SEQ * DH;
    const float* Vg = g_qkv + ((size_t)((2 * BS + b) * HEADS + h)) * SEQ * DH;
    const float qscale = 0.125f * LOG2E;   // 1/sqrt(64) * log2(e), base-2 softmax

    // Stage Q tile into Ps region (reused for P afterwards; P rows are warp-private)
#pragma unroll
    for (int i = 0; i < 8; i++) {
        int u = tid + i * 256;
        int row = u >> 4, c4 = (u & 15) * 4;
        float4 v = *reinterpret_cast<const float4*>(Qg + (size_t)(qt * 128 + row) * DH + c4);
        float* d = &Ps[row * 132 + c4];
        d[0] = f2tf(v.x * qscale); d[1] = f2tf(v.y * qscale);
        d[2] = f2tf(v.z * qscale); d[3] = f2tf(v.w * qscale);
    }
    __syncthreads();

    int r0 = w * 16 + (lane >> 2);
    unsigned qf[8][4];
#pragma unroll
    for (int kc = 0; kc < 8; kc++) {
        int c = kc * 8 + (lane & 3);
        qf[kc][0] = fbits(Ps[r0 * 132 + c]);
        qf[kc][1] = fbits(Ps[(r0 + 8) * 132 + c]);
        qf[kc][2] = fbits(Ps[r0 * 132 + c + 4]);
        qf[kc][3] = fbits(Ps[(r0 + 8) * 132 + c + 4]);
    }

    float o[8][4];
#pragma unroll
    for (int nt = 0; nt < 8; nt++)
#pragma unroll
        for (int i = 0; i < 4; i++) o[nt][i] = 0.f;
    float mrow0 = -1e30f, mrow1 = -1e30f, lrow0 = 0.f, lrow1 = 0.f;

    for (int kt = 0; kt < SEQ / 128; kt++) {
#pragma unroll
        for (int i = 0; i < 8; i++) {
            int u = tid + i * 256;
            int row = u >> 4, c4 = (u & 15) * 4;
            float4 kv = *reinterpret_cast<const float4*>(Kg + (size_t)(kt * 128 + row) * DH + c4);
            float* dk = &Ks[row * 68 + c4];
            dk[0] = f2tf(kv.x); dk[1] = f2tf(kv.y); dk[2] = f2tf(kv.z); dk[3] = f2tf(kv.w);
            float4 vv = *reinterpret_cast<const float4*>(Vg + (size_t)(kt * 128 + row) * DH + c4);
            float* dv = &Vs[row * 68 + c4];
            dv[0] = f2tf(vv.x); dv[1] = f2tf(vv.y); dv[2] = f2tf(vv.z); dv[3] = f2tf(vv.w);
        }
        if (tid < 128) Ms[tid] = mask[b * SEQ + kt * 128 + tid] * LOG2E;
        __syncthreads();

        // S = Q K^T (base-2, scaled)
        float sf[16][4];
#pragma unroll
        for (int nt = 0; nt < 16; nt++)
#pragma unroll
            for (int i = 0; i < 4; i++) sf[nt][i] = 0.f;
#pragma unroll
        for (int kc = 0; kc < 8; kc++) {
#pragma unroll
            for (int nt = 0; nt < 16; nt++) {
                int col = nt * 8 + (lane >> 2);
                int kk = kc * 8 + (lane & 3);
                unsigned b0 = fbits(Ks[col * 68 + kk]);
                unsigned b1 = fbits(Ks[col * 68 + kk + 4]);
                mma8(sf[nt], qf[kc], b0, b1);
            }
        }

        // mask + online softmax (rows r0 and r0+8; quad = 4 lanes of one row)
        float mx0 = -1e30f, mx1 = -1e30f;
#pragma unroll
        for (int nt = 0; nt < 16; nt++) {
            float m0v = Ms[nt * 8 + 2 * (lane & 3)];
            float m1v = Ms[nt * 8 + 2 * (lane & 3) + 1];
            sf[nt][0] += m0v; sf[nt][1] += m1v;
            sf[nt][2] += m0v; sf[nt][3] += m1v;
            mx0 = fmaxf(mx0, fmaxf(sf[nt][0], sf[nt][1]));
            mx1 = fmaxf(mx1, fmaxf(sf[nt][2], sf[nt][3]));
        }
        mx0 = fmaxf(mx0, __shfl_xor_sync(0xffffffffu, mx0, 1));
        mx0 = fmaxf(mx0, __shfl_xor_sync(0xffffffffu, mx0, 2));
        mx1 = fmaxf(mx1, __shfl_xor_sync(0xffffffffu, mx1, 1));
        mx1 = fmaxf(mx1, __shfl_xor_sync(0xffffffffu, mx1, 2));
        float mn0 = fmaxf(mrow0, mx0), mn1 = fmaxf(mrow1, mx1);
        float al0 = exp2f(mrow0 - mn0), al1 = exp2f(mrow1 - mn1);
        mrow0 = mn0; mrow1 = mn1;

        float ps0 = 0.f, ps1 = 0.f;
#pragma unroll
        for (int nt = 0; nt < 16; nt++) {
            sf[nt][0] = exp2f(sf[nt][0] - mn0); sf[nt][1] = exp2f(sf[nt][1] - mn0);
            sf[nt][2] = exp2f(sf[nt][2] - mn1); sf[nt][3] = exp2f(sf[nt][3] - mn1);
            ps0 += sf[nt][0] + sf[nt][1];
            ps1 += sf[nt][2] + sf[nt][3];
        }
        ps0 += __shfl_xor_sync(0xffffffffu, ps0, 1);
        ps0 += __shfl_xor_sync(0xffffffffu, ps0, 2);
        ps1 += __shfl_xor_sync(0xffffffffu, ps1, 1);
        ps1 += __shfl_xor_sync(0xffffffffu, ps1, 2);
        lrow0 = lrow0 * al0 + ps0;
        lrow1 = lrow1 * al1 + ps1;
#pragma unroll
        for (int nt = 0; nt < 8; nt++) {
            o[nt][0] *= al0; o[nt][1] *= al0;
            o[nt][2] *= al1; o[nt][3] *= al1;
        }

        // P -> warp-private smem (tf32), then O += P V
#pragma unroll
        for (int nt = 0; nt < 16; nt++) {
            int c = nt * 8 + 2 * (lane & 3);
            float2 v0 = make_float2(f2tf(sf[nt][0]), f2tf(sf[nt][1]));
            *reinterpret_cast<float2*>(&Ps[r0 * 132 + c]) = v0;
            float2 v1 = make_float2(f2tf(sf[nt][2]), f2tf(sf[nt][3]));
            *reinterpret_cast<float2*>(&Ps[(r0 + 8) * 132 + c]) = v1;
        }
        __syncwarp();
#pragma unroll
        for (int kc = 0; kc < 16; kc++) {
            unsigned a[4];
            int c = kc * 8 + (lane & 3);
            a[0] = fbits(Ps[r0 * 132 + c]);
            a[1] = fbits(Ps[(r0 + 8) * 132 + c]);
            a[2] = fbits(Ps[r0 * 132 + c + 4]);
            a[3] = fbits(Ps[(r0 + 8) * 132 + c + 4]);
#pragma unroll
            for (int nt = 0; nt < 8; nt++) {
                int dcol = nt * 8 + (lane >> 2);
                int kk = kc * 8 + (lane & 3);
                unsigned b0 = fbits(Vs[kk * 68 + dcol]);
                unsigned b1 = fbits(Vs[(kk + 4) * 68 + dcol]);
                mma8(o[nt], a, b0, b1);
            }
        }
        __syncthreads();
    }

    // Epilogue: O / l, write to [b][s][h*64+d]
    float inv0 = 1.0f / lrow0, inv1 = 1.0f / lrow1;
    int s0 = qt * 128 + r0;
#pragma unroll
    for (int nt = 0; nt < 8; nt++) {
        int d = h * DH + nt * 8 + 2 * (lane & 3);
        float2 v0 = make_float2(o[nt][0] * inv0, o[nt][1] * inv0);
        *reinterpret_cast<float2*>(&out[((size_t)b * SEQ + s0) * HID + d]) = v0;
        float2 v1 = make_float2(o[nt][2] * inv1, o[nt][3] * inv1);
        *reinterpret_cast<float2*>(&out[((size_t)b * SEQ + s0 + 8) * HID + d]) = v1;
    }
}

static const int FLASH_SMEM = (128 * 132 + 2 * 128 * 68 + 128) * (int)sizeof(float);  // 137728

extern "C" void kernel_launch(void* const* d_in, const int* in_sizes, int n_in,
                              void* d_out, int out_size)
{
    (void)in_sizes; (void)n_in; (void)out_size;
    const float* x    = (const float*)d_in[0];
    const float* mask = (const float*)d_in[1];
    const float* Wq = (const float*)d_in[2],  *bq = (const float*)d_in[3];
    const float* Aq = (const float*)d_in[4],  *Bq = (const float*)d_in[5];
    const float* Wk = (const float*)d_in[6],  *bk = (const float*)d_in[7];
    const float* Ak = (const float*)d_in[8],  *Bk = (const float*)d_in[9];
    const float* Wv = (const float*)d_in[10], *bv = (const float*)d_in[11];
    const float* Av = (const float*)d_in[12], *Bv = (const float*)d_in[13];
    float* out = (float*)d_out;

    lora_t_kernel<<<dim3(M_TOT / 8, 3), 256>>>(x, Aq, Ak, Av);
    proj_kernel<<<dim3(M_TOT / 128, HID / 128, 3), 256>>>(x, Wq, bq, Bq, Wk, bk, Bk, Wv, bv, Bv);
    cudaFuncSetAttribute(flash_kernel, cudaFuncAttributeMaxDynamicSharedMemorySize, FLASH_SMEM);
    flash_kernel<<<dim3(SEQ / 128, BS * HEADS), 256, FLASH_SMEM>>>(mask, out);
}

// round 12
// speedup vs baseline: 1.0074x; 1.0074x over previous
#include <cuda_runtime.h>

#define BS 4
#define SEQ 2048
#define HID 1024
#define HEADS 16
#define DH 64
#define RANK 16
#define M_TOT (BS*SEQ)
#define LOG2E 1.4426950408889634f

// Scratch (allocation-free rule: __device__ globals)
__device__ float g_T[3 * M_TOT * RANK];                       // 1.5 MB
__device__ float g_qkv[3LL * BS * HEADS * SEQ * DH];          // 96 MB: [p][b][h][s][d]

__device__ __forceinline__ float f2tf(float x) {
    unsigned u;
    asm("cvt.rna.tf32.f32 %0, %1;" : "=r"(u) : "f"(x));
    return __uint_as_float(u);
}
__device__ __forceinline__ unsigned fbits(float x) { return __float_as_uint(x); }

__device__ __forceinline__ void mma8(float* c, const unsigned* a, unsigned b0, unsigned b1) {
    asm volatile(
        "mma.sync.aligned.m16n8k8.row.col.f32.tf32.tf32.f32 "
        "{%0,%1,%2,%3},{%4,%5,%6,%7},{%8,%9},{%0,%1,%2,%3};"
        : "+f"(c[0]), "+f"(c[1]), "+f"(c[2]), "+f"(c[3])
        : "r"(a[0]), "r"(a[1]), "r"(a[2]), "r"(a[3]), "r"(b0), "r"(b1));
}

// ---------------- K1: T[p][m][r] = (1/RANK) * sum_k x[m][k] * A_p[r][k] ----------------
__global__ __launch_bounds__(256) void lora_t_kernel(
    const float* __restrict__ x,
    const float* __restrict__ Aq, const float* __restrict__ Ak, const float* __restrict__ Av)
{
    int p = blockIdx.y;
    const float* A = (p == 0) ? Aq : ((p == 1) ? Ak : Av);
    int w = threadIdx.x >> 5, lane = threadIdx.x & 31;
    int m = blockIdx.x * 8 + w;
    const float* xr = x + (size_t)m * HID;
    float xv[32];
#pragma unroll
    for (int i = 0; i < 32; i++) xv[i] = xr[lane + 32 * i];
#pragma unroll 1
    for (int r = 0; r < RANK; r++) {
        const float* Ar = A + r * HID;
        float acc = 0.f;
#pragma unroll
        for (int i = 0; i < 32; i++) acc += xv[i] * Ar[lane + 32 * i];
#pragma unroll
        for (int off = 16; off; off >>= 1) acc += __shfl_xor_sync(0xffffffffu, acc, off);
        if (lane == 0) g_T[((size_t)p * M_TOT + m) * RANK + r] = acc * (1.0f / RANK);
    }
}

// ---------------- K2: QKV projection GEMM (tf32 mma), bias + LoRA fused --------------
// out[p][b][h][s][d] = x @ W_p^T + bias_p + T_p @ BL_p^T
__global__ __launch_bounds__(256) void proj_kernel(
    const float* __restrict__ x,
    const float* __restrict__ Wq, const float* __restrict__ bq, const float* __restrict__ BLq,
    const float* __restrict__ Wk, const float* __restrict__ bk, const float* __restrict__ BLk,
    const float* __restrict__ Wv, const float* __restrict__ bv, const float* __restrict__ BLv)
{
    __shared__ float As[128 * 36];  // x tile   [m][k], stride 36 -> conflict-free frags
    __shared__ float Bs[128 * 36];  // W tile   [n][k]
    int p = blockIdx.z;
    const float* W    = (p == 0) ? Wq  : ((p == 1) ? Wk  : Wv);
    const float* bias = (p == 0) ? bq  : ((p == 1) ? bk  : bv);
    const float* BL   = (p == 0) ? BLq : ((p == 1) ? BLk : BLv);

    int tid = threadIdx.x, lane = tid & 31, warp = tid >> 5;
    int wm = warp & 3, wn = warp >> 2;               // 4x2 warp grid -> warp tile 32x64
    int mbase = blockIdx.x * 128, nbase = blockIdx.y * 128;

    float acc[2][8][4];
#pragma unroll
    for (int mt = 0; mt < 2; mt++)
#pragma unroll
        for (int nt = 0; nt < 8; nt++)
#pragma unroll
            for (int i = 0; i < 4; i++) acc[mt][nt][i] = 0.f;

    for (int kt = 0; kt < HID / 32; kt++) {
        int kb = kt * 32;
#pragma unroll
        for (int i = 0; i < 4; i++) {
            int u = tid + i * 256;
            int row = u >> 3, c4 = (u & 7) * 4;
            float4 va = *reinterpret_cast<const float4*>(x + (size_t)(mbase + row) * HID + kb + c4);
            float* da = &As[row * 36 + c4];
            da[0] = f2tf(va.x); da[1] = f2tf(va.y); da[2] = f2tf(va.z); da[3] = f2tf(va.w);
            float4 vb = *reinterpret_cast<const float4*>(W + (size_t)(nbase + row) * HID + kb + c4);
            float* db = &Bs[row * 36 + c4];
            db[0] = f2tf(vb.x); db[1] = f2tf(vb.y); db[2] = f2tf(vb.z); db[3] = f2tf(vb.w);
        }
        __syncthreads();
#pragma unroll
        for (int ks = 0; ks < 4; ks++) {
            unsigned a[2][4];
#pragma unroll
            for (int mt = 0; mt < 2; mt++) {
                int r = wm * 32 + mt * 16 + (lane >> 2);
                int c = ks * 8 + (lane & 3);
                a[mt][0] = fbits(As[r * 36 + c]);
                a[mt][1] = fbits(As[(r + 8) * 36 + c]);
                a[mt][2] = fbits(As[r * 36 + c + 4]);
                a[mt][3] = fbits(As[(r + 8) * 36 + c + 4]);
            }
#pragma unroll
            for (int nt = 0; nt < 8; nt++) {
                int col = wn * 64 + nt * 8 + (lane >> 2);
                unsigned b0 = fbits(Bs[col * 36 + ks * 8 + (lane & 3)]);
                unsigned b1 = fbits(Bs[col * 36 + ks * 8 + 4 + (lane & 3)]);
                mma8(acc[0][nt], a[0], b0, b1);
                mma8(acc[1][nt], a[1], b0, b1);
            }
        }
        __syncthreads();
    }

    // LoRA correction: 16 extra K-columns (T already scaled by 1/RANK)
#pragma unroll
    for (int i = 0; i < 8; i++) {
        int u = tid + i * 256;
        int row = u >> 4, c = u & 15;
        As[row * 36 + c] = f2tf(g_T[((size_t)p * M_TOT + mbase + row) * RANK + c]);
        Bs[row * 36 + c] = f2tf(BL[(size_t)(nbase + row) * RANK + c]);
    }
    __syncthreads();
#pragma unroll
    for (int ks = 0; ks < 2; ks++) {
        unsigned a[2][4];
#pragma unroll
        for (int mt = 0; mt < 2; mt++) {
            int r = wm * 32 + mt * 16 + (lane >> 2);
            int c = ks * 8 + (lane & 3);
            a[mt][0] = fbits(As[r * 36 + c]);
            a[mt][1] = fbits(As[(r + 8) * 36 + c]);
            a[mt][2] = fbits(As[r * 36 + c + 4]);
            a[mt][3] = fbits(As[(r + 8) * 36 + c + 4]);
        }
#pragma unroll
        for (int nt = 0; nt < 8; nt++) {
            int col = wn * 64 + nt * 8 + (lane >> 2);
            unsigned b0 = fbits(Bs[col * 36 + ks * 8 + (lane & 3)]);
            unsigned b1 = fbits(Bs[col * 36 + ks * 8 + 4 + (lane & 3)]);
            mma8(acc[0][nt], a[0], b0, b1);
            mma8(acc[1][nt], a[1], b0, b1);
        }
    }

    // Epilogue: bias, permute to [p][b][h][s][d]
#pragma unroll
    for (int mt = 0; mt < 2; mt++) {
#pragma unroll
        for (int half = 0; half < 2; half++) {
            int m = mbase + wm * 32 + mt * 16 + (lane >> 2) + half * 8;
            int bb = m >> 11, s = m & (SEQ - 1);
#pragma unroll
            for (int nt = 0; nt < 8; nt++) {
                int n = nbase + wn * 64 + nt * 8 + 2 * (lane & 3);
                float2 v;
                v.x = acc[mt][nt][half * 2 + 0] + bias[n];
                v.y = acc[mt][nt][half * 2 + 1] + bias[n + 1];
                int hh = n >> 6, d = n & 63;
                *reinterpret_cast<float2*>(
                    &g_qkv[((((size_t)p * BS + bb) * HEADS + hh) * SEQ + s) * DH + d]) = v;
            }
        }
    }
}

// ---------------- K3: flash attention (tf32 mma, fp32 online softmax) ----------------
// grid (SEQ/128, BS*HEADS), 256 threads, 8 warps x 16 q-rows
__global__ __launch_bounds__(256) void flash_kernel(const float* __restrict__ mask,
                                                    float* __restrict__ out)
{
    extern __shared__ float sm[];
    float* Ps = sm;                  // 128*132 (also Q staging)
    float* Ks = sm + 128 * 132;      // 128*68
    float* Vs = Ks + 128 * 68;       // 128*68
    float* Ms = Vs + 128 * 68;       // 128

    int tid = threadIdx.x, lane = tid & 31, w = tid >> 5;
    int qt = blockIdx.x, bh = blockIdx.y;
    int b = bh >> 4, h = bh & 15;
    const float* Qg = g_qkv + ((size_t)(b * HEADS + h)) * SEQ * DH;
    const float* Kg = g_qkv + ((size_t)((BS + b) * HEADS + h)) * SEQ * DH;
    const float* Vg = g_qkv + ((size_t)((2 * BS + b) * HEADS + h)) * SEQ * DH;
    const float qscale = 0.125f * LOG2E;   // 1/sqrt(64) * log2(e), base-2 softmax

    // Stage Q tile into Ps region (reused for P afterwards; P rows are warp-private)
#pragma unroll
    for (int i = 0; i < 8; i++) {
        int u = tid + i * 256;
        int row = u >> 4, c4 = (u & 15) * 4;
        float4 v = *reinterpret_cast<const float4*>(Qg + (size_t)(qt * 128 + row) * DH + c4);
        float* d = &Ps[row * 132 + c4];
        d[0] = f2tf(v.x * qscale); d[1] = f2tf(v.y * qscale);
        d[2] = f2tf(v.z * qscale); d[3] = f2tf(v.w * qscale);
    }
    __syncthreads();

    int r0 = w * 16 + (lane >> 2);
    unsigned qf[8][4];
#pragma unroll
    for (int kc = 0; kc < 8; kc++) {
        int c = kc * 8 + (lane & 3);
        qf[kc][0] = fbits(Ps[r0 * 132 + c]);
        qf[kc][1] = fbits(Ps[(r0 + 8) * 132 + c]);
        qf[kc][2] = fbits(Ps[r0 * 132 + c + 4]);
        qf[kc][3] = fbits(Ps[(r0 + 8) * 132 + c + 4]);
    }

    float o[8][4];
#pragma unroll
    for (int nt = 0; nt < 8; nt++)
#pragma unroll
        for (int i = 0; i < 4; i++) o[nt][i] = 0.f;
    float mrow0 = -1e30f, mrow1 = -1e30f, lrow0 = 0.f, lrow1 = 0.f;

    for (int kt = 0; kt < SEQ / 128; kt++) {
#pragma unroll
        for (int i = 0; i < 8; i++) {
            int u = tid + i * 256;
            int row = u >> 4, c4 = (u & 15) * 4;
            float4 kv = *reinterpret_cast<const float4*>(Kg + (size_t)(kt * 128 + row) * DH + c4);
            float* dk = &Ks[row * 68 + c4];
            dk[0] = f2tf(kv.x); dk[1] = f2tf(kv.y); dk[2] = f2tf(kv.z); dk[3] = f2tf(kv.w);
            float4 vv = *reinterpret_cast<const float4*>(Vg + (size_t)(kt * 128 + row) * DH + c4);
            float* dv = &Vs[row * 68 + c4];
            dv[0] = f2tf(vv.x); dv[1] = f2tf(vv.y); dv[2] = f2tf(vv.z); dv[3] = f2tf(vv.w);
        }
        if (tid < 128) Ms[tid] = mask[b * SEQ + kt * 128 + tid] * LOG2E;
        __syncthreads();

        // S = Q K^T (base-2, scaled)
        float sf[16][4];
#pragma unroll
        for (int nt = 0; nt < 16; nt++)
#pragma unroll
            for (int i = 0; i < 4; i++) sf[nt][i] = 0.f;
#pragma unroll
        for (int kc = 0; kc < 8; kc++) {
#pragma unroll
            for (int nt = 0; nt < 16; nt++) {
                int col = nt * 8 + (lane >> 2);
                int kk = kc * 8 + (lane & 3);
                unsigned b0 = fbits(Ks[col * 68 + kk]);
                unsigned b1 = fbits(Ks[col * 68 + kk + 4]);
                mma8(sf[nt], qf[kc], b0, b1);
            }
        }

        // mask + online softmax (rows r0 and r0+8; quad = 4 lanes of one row)
        float mx0 = -1e30f, mx1 = -1e30f;
#pragma unroll
        for (int nt = 0; nt < 16; nt++) {
            float m0v = Ms[nt * 8 + 2 * (lane & 3)];
            float m1v = Ms[nt * 8 + 2 * (lane & 3) + 1];
            sf[nt][0] += m0v; sf[nt][1] += m1v;
            sf[nt][2] += m0v; sf[nt][3] += m1v;
            mx0 = fmaxf(mx0, fmaxf(sf[nt][0], sf[nt][1]));
            mx1 = fmaxf(mx1, fmaxf(sf[nt][2], sf[nt][3]));
        }
        mx0 = fmaxf(mx0, __shfl_xor_sync(0xffffffffu, mx0, 1));
        mx0 = fmaxf(mx0, __shfl_xor_sync(0xffffffffu, mx0, 2));
        mx1 = fmaxf(mx1, __shfl_xor_sync(0xffffffffu, mx1, 1));
        mx1 = fmaxf(mx1, __shfl_xor_sync(0xffffffffu, mx1, 2));
        float mn0 = fmaxf(mrow0, mx0), mn1 = fmaxf(mrow1, mx1);
        float al0 = exp2f(mrow0 - mn0), al1 = exp2f(mrow1 - mn1);
        mrow0 = mn0; mrow1 = mn1;

        float ps0 = 0.f, ps1 = 0.f;
#pragma unroll
        for (int nt = 0; nt < 16; nt++) {
            sf[nt][0] = exp2f(sf[nt][0] - mn0); sf[nt][1] = exp2f(sf[nt][1] - mn0);
            sf[nt][2] = exp2f(sf[nt][2] - mn1); sf[nt][3] = exp2f(sf[nt][3] - mn1);
            ps0 += sf[nt][0] + sf[nt][1];
            ps1 += sf[nt][2] + sf[nt][3];
        }
        ps0 += __shfl_xor_sync(0xffffffffu, ps0, 1);
        ps0 += __shfl_xor_sync(0xffffffffu, ps0, 2);
        ps1 += __shfl_xor_sync(0xffffffffu, ps1, 1);
        ps1 += __shfl_xor_sync(0xffffffffu, ps1, 2);
        lrow0 = lrow0 * al0 + ps0;
        lrow1 = lrow1 * al1 + ps1;
#pragma unroll
        for (int nt = 0; nt < 8; nt++) {
            o[nt][0] *= al0; o[nt][1] *= al0;
            o[nt][2] *= al1; o[nt][3] *= al1;
        }

        // P -> warp-private smem (tf32), then O += P V
#pragma unroll
        for (int nt = 0; nt < 16; nt++) {
            int c = nt * 8 + 2 * (lane & 3);
            float2 v0 = make_float2(f2tf(sf[nt][0]), f2tf(sf[nt][1]));
            *reinterpret_cast<float2*>(&Ps[r0 * 132 + c]) = v0;
            float2 v1 = make_float2(f2tf(sf[nt][2]), f2tf(sf[nt][3]));
            *reinterpret_cast<float2*>(&Ps[(r0 + 8) * 132 + c]) = v1;
        }
        __syncwarp();
#pragma unroll
        for (int kc = 0; kc < 16; kc++) {
            unsigned a[4];
            int c = kc * 8 + (lane & 3);
            a[0] = fbits(Ps[r0 * 132 + c]);
            a[1] = fbits(Ps[(r0 + 8) * 132 + c]);
            a[2] = fbits(Ps[r0 * 132 + c + 4]);
            a[3] = fbits(Ps[(r0 + 8) * 132 + c + 4]);
#pragma unroll
            for (int nt = 0; nt < 8; nt++) {
                int dcol = nt * 8 + (lane >> 2);
                int kk = kc * 8 + (lane & 3);
                unsigned b0 = fbits(Vs[kk * 68 + dcol]);
                unsigned b1 = fbits(Vs[(kk + 4) * 68 + dcol]);
                mma8(o[nt], a, b0, b1);
            }
        }
        __syncthreads();
    }

    // Epilogue: O / l, write to [b][s][h*64+d]
    float inv0 = 1.0f / lrow0, inv1 = 1.0f / lrow1;
    int s0 = qt * 128 + r0;
#pragma unroll
    for (int nt = 0; nt < 8; nt++) {
        int d = h * DH + nt * 8 + 2 * (lane & 3);
        float2 v0 = make_float2(o[nt][0] * inv0, o[nt][1] * inv0);
        *reinterpret_cast<float2*>(&out[((size_t)b * SEQ + s0) * HID + d]) = v0;
        float2 v1 = make_float2(o[nt][2] * inv1, o[nt][3] * inv1);
        *reinterpret_cast<float2*>(&out[((size_t)b * SEQ + s0 + 8) * HID + d]) = v1;
    }
}

static const int FLASH_SMEM = (128 * 132 + 2 * 128 * 68 + 128) * (int)sizeof(float);  // 137728

extern "C" void kernel_launch(void* const* d_in, const int* in_sizes, int n_in,
                              void* d_out, int out_size)
{
    (void)in_sizes; (void)n_in; (void)out_size;
    const float* x    = (const float*)d_in[0];
    const float* mask = (const float*)d_in[1];
    const float* Wq = (const float*)d_in[2],  *bq = (const float*)d_in[3];
    const float* Aq = (const float*)d_in[4],  *Bq = (const float*)d_in[5];
    const float* Wk = (const float*)d_in[6],  *bk = (const float*)d_in[7];
    const float* Ak = (const float*)d_in[8],  *Bk = (const float*)d_in[9];
    const float* Wv = (const float*)d_in[10], *bv = (const float*)d_in[11];
    const float* Av = (const float*)d_in[12], *Bv = (const float*)d_in[13];
    float* out = (float*)d_out;

    lora_t_kernel<<<dim3(M_TOT / 8, 3), 256>>>(x, Aq, Ak, Av);
    proj_kernel<<<dim3(M_TOT / 128, HID / 128, 3), 256>>>(x, Wq, bq, Bq, Wk, bk, Bk, Wv, bv, Bv);
    cudaFuncSetAttribute(flash_kernel, cudaFuncAttributeMaxDynamicSharedMemorySize, FLASH_SMEM);
    flash_kernel<<<dim3(SEQ / 128, BS * HEADS), 256, FLASH_SMEM>>>(mask, out);
}